// round 2
// baseline (speedup 1.0000x reference)
#include <cuda_runtime.h>
#include <cstdint>
#include <cstddef>

// ---------------- problem constants ----------------
#define T_STEPS 16384
#define HDIM    512
#define GDIM    1536          // 3*H
// scan decomposition
#define NCTA    32
#define HPC     16            // HDIM / NCTA  (h elements per CTA)
#define RPC     48            // GDIM / NCTA  (W_hh rows per CTA: 3 gates x HPC)
#define NTH     384           // RPC * 8 threads (8 lanes per row)

// ---------------- device scratch ----------------
__device__ float    g_gi[(size_t)T_STEPS * GDIM];  // precomputed input gates (100 MB)
__device__ float    g_h[2][HDIM];                  // double-buffered hidden state
__device__ unsigned g_flag[NCTA];                  // per-CTA epoch flags

// ---------------- init: reset state each launch ----------------
__global__ void scan_init() {
    int t = threadIdx.x;
    if (t < HDIM) g_h[0][t] = 0.f;
    if (t < NCTA) g_flag[t] = 0u;
}

// ---------------- GEMM: gi = x @ W_ih^T + b_ih ----------------
#define BM 128
#define BN 128
#define BK 8

__global__ void __launch_bounds__(256) gemm_gi(
    const float* __restrict__ x, const float* __restrict__ Wih,
    const float* __restrict__ bih) {
    __shared__ __align__(16) float As[BK][BM];
    __shared__ __align__(16) float Bs[BK][BN];
    const int bn  = blockIdx.x;        // 0..11
    const int bm  = blockIdx.y;        // 0..127
    const int tid = threadIdx.x;
    const int tx  = tid & 15;
    const int ty  = tid >> 4;

    const int lrow = tid >> 1;
    const int lseg = (tid & 1) * 4;
    const float* xp = x   + (size_t)(bm * BM + lrow) * HDIM + lseg;
    const float* wp = Wih + (size_t)(bn * BN + lrow) * HDIM + lseg;

    float acc[8][8];
#pragma unroll
    for (int i = 0; i < 8; i++)
#pragma unroll
        for (int j = 0; j < 8; j++) acc[i][j] = 0.f;

    for (int k0 = 0; k0 < HDIM; k0 += BK) {
        float4 av = *(const float4*)(xp + k0);
        float4 bv = *(const float4*)(wp + k0);
        As[lseg + 0][lrow] = av.x; As[lseg + 1][lrow] = av.y;
        As[lseg + 2][lrow] = av.z; As[lseg + 3][lrow] = av.w;
        Bs[lseg + 0][lrow] = bv.x; Bs[lseg + 1][lrow] = bv.y;
        Bs[lseg + 2][lrow] = bv.z; Bs[lseg + 3][lrow] = bv.w;
        __syncthreads();
#pragma unroll
        for (int k = 0; k < BK; k++) {
            float4 a0 = *(const float4*)&As[k][ty * 8];
            float4 a1 = *(const float4*)&As[k][ty * 8 + 4];
            float4 b0 = *(const float4*)&Bs[k][tx * 8];
            float4 b1 = *(const float4*)&Bs[k][tx * 8 + 4];
            float a[8] = {a0.x, a0.y, a0.z, a0.w, a1.x, a1.y, a1.z, a1.w};
            float b[8] = {b0.x, b0.y, b0.z, b0.w, b1.x, b1.y, b1.z, b1.w};
#pragma unroll
            for (int i = 0; i < 8; i++)
#pragma unroll
                for (int j = 0; j < 8; j++)
                    acc[i][j] = fmaf(a[i], b[j], acc[i][j]);
        }
        __syncthreads();
    }
#pragma unroll
    for (int i = 0; i < 8; i++) {
        int row = bm * BM + ty * 8 + i;
        float* gp = &g_gi[(size_t)row * GDIM + bn * BN + tx * 8];
#pragma unroll
        for (int j = 0; j < 8; j++)
            gp[j] = acc[i][j] + bih[bn * BN + tx * 8 + j];
    }
}

// ---------------- scan helpers ----------------
__device__ __forceinline__ float f32x2_hsum(unsigned long long a) {
    float lo, hi;
    asm("mov.b64 {%0,%1}, %2;" : "=f"(lo), "=f"(hi) : "l"(a));
    return lo + hi;
}
__device__ __forceinline__ float fast_sigmoid(float x) {
    return __fdividef(1.f, 1.f + __expf(-x));
}
__device__ __forceinline__ float fast_tanh(float x) {
    x = fminf(fmaxf(x, -20.f), 20.f);
    float e = __expf(2.f * x);
    return __fdividef(e - 1.f, e + 1.f);
}

// ---------------- persistent GRU scan ----------------
__global__ void __launch_bounds__(NTH, 1) gru_scan(
    const float* __restrict__ Whh, const float* __restrict__ bhh,
    float* __restrict__ out) {
    __shared__ float red_s[RPC];
    __shared__ float gi_s[2][RPC];
    __shared__ float bhh_s[RPC];

    const int c    = blockIdx.x;
    const int tid  = threadIdx.x;
    const int lr   = tid >> 3;           // local row 0..47
    const int j    = tid & 7;            // lane within row
    const int lane = tid & 31;

    // global row for this thread's W_hh row
    const int gr = (lr / HPC) * HDIM + c * HPC + (lr % HPC);

    // ---- weights resident in registers: 16 x (u64,u64) = 64 regs ----
    unsigned long long wlo[16], whi[16];
    {
        const ulonglong2* wp =
            (const ulonglong2*)(Whh + (size_t)gr * HDIM + j * 4);
#pragma unroll
        for (int s = 0; s < 16; ++s) {
            ulonglong2 wv = __ldg(wp + s * 8);   // stride 128B
            wlo[s] = wv.x; whi[s] = wv.y;
        }
    }

    // gi row index for tid<RPC
    const int gr2 = (tid / HPC) * HDIM + c * HPC + (tid % HPC);
    if (tid < RPC) {
        bhh_s[tid]   = bhh[gr2];
        gi_s[0][tid] = g_gi[gr2];        // gi for t=0
    }
    const int hbase = c * HPC;
    float hprev = 0.f;                   // gate threads carry own h in regs
    __syncthreads();

    for (int t = 0; t < T_STEPS; ++t) {
        const int par = t & 1;

        // ---- wait until h(t) is published by all CTAs (every warp polls) ----
        if (t > 0) {
            const unsigned tgt = (unsigned)t;
            unsigned* fp = &g_flag[lane & (NCTA - 1)];
            for (;;) {
                unsigned f;
                asm volatile("ld.acquire.gpu.global.u32 %0, [%1];"
                             : "=r"(f) : "l"(fp));
                if (__all_sync(0xffffffffu, f >= tgt)) break;
            }
        }

        // prefetch gi(t+1) into registers (hides under matvec)
        float gi_pf = 0.f;
        const bool pf = (tid < RPC) && (t + 1 < T_STEPS);
        if (pf) gi_pf = __ldg(&g_gi[(size_t)(t + 1) * GDIM + gr2]);

        // ---- matvec: weights from regs, h fresh from L2 (.cv) ----
        const char* hp = (const char*)(g_h[par] + j * 4);
        unsigned long long a0 = 0ull, a1 = 0ull;
#pragma unroll
        for (int s = 0; s < 16; ++s) {
            unsigned long long h0, h1;
            asm volatile("ld.global.cv.v2.u64 {%0,%1}, [%2];"
                         : "=l"(h0), "=l"(h1) : "l"(hp + s * 128));
            asm("fma.rn.f32x2 %0, %1, %2, %0;" : "+l"(a0) : "l"(wlo[s]), "l"(h0));
            asm("fma.rn.f32x2 %0, %1, %2, %0;" : "+l"(a1) : "l"(whi[s]), "l"(h1));
        }
        float acc = f32x2_hsum(a0) + f32x2_hsum(a1);
        acc += __shfl_xor_sync(0xffffffffu, acc, 4);
        acc += __shfl_xor_sync(0xffffffffu, acc, 2);
        acc += __shfl_xor_sync(0xffffffffu, acc, 1);
        if (j == 0) red_s[lr] = acc;
        if (pf) gi_s[par ^ 1][tid] = gi_pf;
        __syncthreads();                 // the ONE barrier per step

        // ---- gate math + publish (warp 0 only; other warps race to poll) ----
        if (tid < HPC) {
            const int i = tid;
            float ghr = red_s[i]           + bhh_s[i];
            float ghz = red_s[HPC + i]     + bhh_s[HPC + i];
            float ghn = red_s[2 * HPC + i] + bhh_s[2 * HPC + i];
            float gir = gi_s[par][i];
            float giz = gi_s[par][HPC + i];
            float gin = gi_s[par][2 * HPC + i];
            float r = fast_sigmoid(gir + ghr);
            float z = fast_sigmoid(giz + ghz);
            float n = fast_tanh(gin + r * ghn);
            float hnew = n + z * (hprev - n);   // (1-z)*n + z*h
            hprev = hnew;
            out[(size_t)t * HDIM + hbase + i] = hnew;
            asm volatile("st.relaxed.gpu.global.f32 [%0], %1;"
                         :: "l"(&g_h[par ^ 1][hbase + i]), "f"(hnew));
        }
        if ((tid >> 5) == 0) {
            __syncwarp();
            if (tid == 0) {
                asm volatile("st.release.gpu.global.u32 [%0], %1;"
                             :: "l"(&g_flag[c]), "r"((unsigned)(t + 1)));
            }
        }
    }
}

// ---------------- launch ----------------
extern "C" void kernel_launch(void* const* d_in, const int* in_sizes, int n_in,
                              void* d_out, int out_size) {
    const float* x   = (const float*)d_in[0];
    const float* Wih = (const float*)d_in[1];
    const float* Whh = (const float*)d_in[2];
    const float* bih = (const float*)d_in[3];
    const float* bhh = (const float*)d_in[4];
    float* out = (float*)d_out;

    scan_init<<<1, 512>>>();
    dim3 ggrid(GDIM / BN, T_STEPS / BM);   // (12, 128)
    gemm_gi<<<ggrid, 256>>>(x, Wih, bih);
    gru_scan<<<NCTA, NTH>>>(Whh, bhh, out);
}

// round 3
// speedup vs baseline: 1.6892x; 1.6892x over previous
#include <cuda_runtime.h>
#include <cstdint>
#include <cstddef>

// ---------------- problem constants ----------------
#define T_STEPS 16384
#define HDIM    512
#define GDIM    1536          // 3*H
// scan decomposition
#define NCTA    32
#define HPC     16            // HDIM / NCTA  (h elements per CTA)
#define RPC     48            // GDIM / NCTA  (W_hh rows per CTA: 3 gates x HPC)
#define NTH     384           // RPC * 8 threads (8 lanes per row)
#define POLLW   11            // warp that polls the global counter

// ---------------- device scratch ----------------
__device__ float    g_gi[(size_t)T_STEPS * GDIM];  // precomputed input gates (100 MB)
__device__ float    g_h[2][HDIM];                  // double-buffered hidden state
__device__ unsigned g_cnt;                         // single barrier counter

// ---------------- init: reset state each launch ----------------
__global__ void scan_init() {
    int t = threadIdx.x;
    if (t < HDIM) g_h[0][t] = 0.f;
    if (t == 0)   g_cnt = 0u;
}

// ---------------- GEMM: gi = x @ W_ih^T + b_ih ----------------
#define BM 128
#define BN 128
#define BK 8

__global__ void __launch_bounds__(256) gemm_gi(
    const float* __restrict__ x, const float* __restrict__ Wih,
    const float* __restrict__ bih) {
    __shared__ __align__(16) float As[BK][BM];
    __shared__ __align__(16) float Bs[BK][BN];
    const int bn  = blockIdx.x;        // 0..11
    const int bm  = blockIdx.y;        // 0..127
    const int tid = threadIdx.x;
    const int tx  = tid & 15;
    const int ty  = tid >> 4;

    const int lrow = tid >> 1;
    const int lseg = (tid & 1) * 4;
    const float* xp = x   + (size_t)(bm * BM + lrow) * HDIM + lseg;
    const float* wp = Wih + (size_t)(bn * BN + lrow) * HDIM + lseg;

    float acc[8][8];
#pragma unroll
    for (int i = 0; i < 8; i++)
#pragma unroll
        for (int j = 0; j < 8; j++) acc[i][j] = 0.f;

    for (int k0 = 0; k0 < HDIM; k0 += BK) {
        float4 av = *(const float4*)(xp + k0);
        float4 bv = *(const float4*)(wp + k0);
        As[lseg + 0][lrow] = av.x; As[lseg + 1][lrow] = av.y;
        As[lseg + 2][lrow] = av.z; As[lseg + 3][lrow] = av.w;
        Bs[lseg + 0][lrow] = bv.x; Bs[lseg + 1][lrow] = bv.y;
        Bs[lseg + 2][lrow] = bv.z; Bs[lseg + 3][lrow] = bv.w;
        __syncthreads();
#pragma unroll
        for (int k = 0; k < BK; k++) {
            float4 a0 = *(const float4*)&As[k][ty * 8];
            float4 a1 = *(const float4*)&As[k][ty * 8 + 4];
            float4 b0 = *(const float4*)&Bs[k][tx * 8];
            float4 b1 = *(const float4*)&Bs[k][tx * 8 + 4];
            float a[8] = {a0.x, a0.y, a0.z, a0.w, a1.x, a1.y, a1.z, a1.w};
            float b[8] = {b0.x, b0.y, b0.z, b0.w, b1.x, b1.y, b1.z, b1.w};
#pragma unroll
            for (int i = 0; i < 8; i++)
#pragma unroll
                for (int j = 0; j < 8; j++)
                    acc[i][j] = fmaf(a[i], b[j], acc[i][j]);
        }
        __syncthreads();
    }
#pragma unroll
    for (int i = 0; i < 8; i++) {
        int row = bm * BM + ty * 8 + i;
        float* gp = &g_gi[(size_t)row * GDIM + bn * BN + tx * 8];
#pragma unroll
        for (int j = 0; j < 8; j++)
            gp[j] = acc[i][j] + bih[bn * BN + tx * 8 + j];
    }
}

// ---------------- scan helpers ----------------
__device__ __forceinline__ float f32x2_hsum(unsigned long long a) {
    float lo, hi;
    asm("mov.b64 {%0,%1}, %2;" : "=f"(lo), "=f"(hi) : "l"(a));
    return lo + hi;
}
__device__ __forceinline__ float fast_sigmoid(float x) {
    return __fdividef(1.f, 1.f + __expf(-x));
}
__device__ __forceinline__ float fast_tanh(float x) {
    x = fminf(fmaxf(x, -20.f), 20.f);
    float e = __expf(2.f * x);
    return __fdividef(e - 1.f, e + 1.f);
}

// ---------------- persistent GRU scan ----------------
__global__ void __launch_bounds__(NTH, 1) gru_scan(
    const float* __restrict__ Whh, const float* __restrict__ bhh,
    float* __restrict__ out) {
    __shared__ float red_s[RPC];
    __shared__ float gi_s[2][RPC];
    __shared__ float bhh_s[RPC];

    const int c    = blockIdx.x;
    const int tid  = threadIdx.x;
    const int wid  = tid >> 5;
    const int lr   = tid >> 3;           // local row 0..47
    const int j    = tid & 7;            // lane within row

    // global row for this thread's W_hh row (gate-major: r,z,n blocks of HPC)
    const int gr = (lr / HPC) * HDIM + c * HPC + (lr % HPC);

    // ---- weights resident in registers: 16 x (u64,u64) = 64 regs ----
    unsigned long long wlo[16], whi[16];
    {
        const ulonglong2* wp =
            (const ulonglong2*)(Whh + (size_t)gr * HDIM + j * 4);
#pragma unroll
        for (int s = 0; s < 16; ++s) {
            ulonglong2 wv = __ldg(wp + s * 8);   // stride 128B
            wlo[s] = wv.x; whi[s] = wv.y;
        }
    }

    // gi row index for tid<RPC
    const int gr2 = (tid / HPC) * HDIM + c * HPC + (tid % HPC);
    if (tid < RPC) {
        bhh_s[tid]   = bhh[gr2];
        gi_s[0][tid] = g_gi[gr2];        // gi for t=0
    }
    const int hbase = c * HPC;
    float hprev = 0.f;                   // gate threads carry own h in regs
    __syncthreads();

    for (int t = 0; t < T_STEPS; ++t) {
        const int par = t & 1;

        // prefetch gi(t+1) into registers BEFORE the wait (hides under poll)
        float gi_pf = 0.f;
        const bool pf = (tid < RPC) && (t + 1 < T_STEPS);
        if (pf) gi_pf = __ldg(&g_gi[(size_t)(t + 1) * GDIM + gr2]);

        // ---- barrier: one poller warp, lane-uniform broadcast load ----
        if (t > 0) {
            if (wid == POLLW) {
                const unsigned tgt = 32u * (unsigned)t;
                unsigned f;
                do {
                    asm volatile("ld.acquire.gpu.global.u32 %0, [%1];"
                                 : "=r"(f) : "l"(&g_cnt));
                } while (f < tgt);
            }
            __syncthreads();             // bar A: release all warps
        }

        // ---- matvec: weights from regs, h fresh from L2 (.cg) ----
        const char* hp = (const char*)(g_h[par]) + (size_t)j * 16;
        unsigned long long a0 = 0ull, a1 = 0ull, a2 = 0ull, a3 = 0ull;
#pragma unroll
        for (int s = 0; s < 16; s += 2) {
            unsigned long long h0, h1, h2, h3;
            asm volatile("ld.global.cg.v2.u64 {%0,%1}, [%2];"
                         : "=l"(h0), "=l"(h1) : "l"(hp + s * 128));
            asm volatile("ld.global.cg.v2.u64 {%0,%1}, [%2];"
                         : "=l"(h2), "=l"(h3) : "l"(hp + (s + 1) * 128));
            asm("fma.rn.f32x2 %0, %1, %2, %0;" : "+l"(a0) : "l"(wlo[s]),     "l"(h0));
            asm("fma.rn.f32x2 %0, %1, %2, %0;" : "+l"(a1) : "l"(whi[s]),     "l"(h1));
            asm("fma.rn.f32x2 %0, %1, %2, %0;" : "+l"(a2) : "l"(wlo[s + 1]), "l"(h2));
            asm("fma.rn.f32x2 %0, %1, %2, %0;" : "+l"(a3) : "l"(whi[s + 1]), "l"(h3));
        }
        float acc = (f32x2_hsum(a0) + f32x2_hsum(a1)) +
                    (f32x2_hsum(a2) + f32x2_hsum(a3));
        acc += __shfl_xor_sync(0xffffffffu, acc, 4);
        acc += __shfl_xor_sync(0xffffffffu, acc, 2);
        acc += __shfl_xor_sync(0xffffffffu, acc, 1);
        if (j == 0) red_s[lr] = acc;
        if (pf) gi_s[par ^ 1][tid] = gi_pf;
        __syncthreads();                 // bar B: red_s/gi_s ready

        // ---- gate math + publish (warp 0) ----
        if (wid == 0) {
            if (tid < HPC) {
                const int i = tid;
                float ghr = red_s[i]           + bhh_s[i];
                float ghz = red_s[HPC + i]     + bhh_s[HPC + i];
                float ghn = red_s[2 * HPC + i] + bhh_s[2 * HPC + i];
                float gir = gi_s[par][i];
                float giz = gi_s[par][HPC + i];
                float gin = gi_s[par][2 * HPC + i];
                float r = fast_sigmoid(gir + ghr);
                float z = fast_sigmoid(giz + ghz);
                float n = fast_tanh(gin + r * ghn);
                float hnew = n + z * (hprev - n);   // (1-z)*n + z*h
                hprev = hnew;
                out[(size_t)t * HDIM + hbase + i] = hnew;
                asm volatile("st.global.cg.f32 [%0], %1;"
                             :: "l"(&g_h[par ^ 1][hbase + i]), "f"(hnew));
            }
            __syncwarp();
            if (tid == 0) {
                asm volatile("fence.acq_rel.gpu;");
                asm volatile("red.relaxed.gpu.global.add.u32 [%0], %1;"
                             :: "l"(&g_cnt), "r"(1u));
            }
        }
    }
}

// ---------------- launch ----------------
extern "C" void kernel_launch(void* const* d_in, const int* in_sizes, int n_in,
                              void* d_out, int out_size) {
    const float* x   = (const float*)d_in[0];
    const float* Wih = (const float*)d_in[1];
    const float* Whh = (const float*)d_in[2];
    const float* bih = (const float*)d_in[3];
    const float* bhh = (const float*)d_in[4];
    float* out = (float*)d_out;

    scan_init<<<1, 512>>>();
    dim3 ggrid(GDIM / BN, T_STEPS / BM);   // (12, 128)
    gemm_gi<<<ggrid, 256>>>(x, Wih, bih);
    gru_scan<<<NCTA, NTH>>>(Whh, bhh, out);
}